// round 3
// baseline (speedup 1.0000x reference)
#include <cuda_runtime.h>

// Conv2d 3x3, stride 1, pad 1, NCHW fp32.
// x: [32, 64, 112, 112], w: [128, 64, 3, 3], b: [128] -> out: [32, 128, 112, 112]

#define CN 32
#define CC 64
#define CH 112
#define CW 112
#define CK 128

#define OC_TILE 32   // output channels per block
#define H_TILE  16   // output rows per block
#define W_TILE  28   // output cols per block
#define ICB      8   // input-channel chunk staged in smem
#define PW       7   // pixels (width) per thread
#define IN_H    (H_TILE + 2)   // 18
#define IN_W    (W_TILE + 2)   // 30
#define IN_STRIDE 33           // padded row stride (bank-conflict break)

__global__ __launch_bounds__(256, 2)
void conv3x3_kernel(const float* __restrict__ x,
                    const float* __restrict__ wgt,
                    const float* __restrict__ bias,
                    float* __restrict__ out) {
    __shared__ float s_in[ICB][IN_H][IN_STRIDE];          // 19,008 B
    __shared__ float s_w[ICB * 9 * OC_TILE];              //  9,216 B  layout [ic][kh][kw][oc]

    const int tid  = threadIdx.x;
    const int wseg = tid & 3;          // 0..3  -> w segment of 7
    const int row  = (tid >> 2) & 15;  // 0..15 -> output row in tile
    const int ocg  = tid >> 6;         // 0..3  -> group of 8 ocs

    const int sp = blockIdx.x;         // 0..27 = hb*4 + wb
    const int hb = sp >> 2;            // 0..6
    const int wb = sp & 3;             // 0..3
    const int ocb = blockIdx.y * OC_TILE;
    const int n   = blockIdx.z;

    const int h0 = hb * H_TILE - 1;    // input tile origin (with halo)
    const int w0 = wb * W_TILE - 1;

    float acc[8][PW];
#pragma unroll
    for (int o = 0; o < 8; o++)
#pragma unroll
        for (int p = 0; p < PW; p++) acc[o][p] = 0.0f;

    const float* xn = x + (size_t)n * CC * CH * CW;

    for (int icb = 0; icb < CC; icb += ICB) {
        __syncthreads();   // protect smem from previous chunk's readers

        // ---- stage input tile: ICB x 18 x 30, zero-padded at image border ----
        for (int idx = tid; idx < ICB * IN_H * IN_W; idx += 256) {
            int ic  = idx / (IN_H * IN_W);
            int rem = idx - ic * (IN_H * IN_W);
            int r   = rem / IN_W;
            int c   = rem - r * IN_W;
            int gh  = h0 + r;
            int gw  = w0 + c;
            float v = 0.0f;
            if ((unsigned)gh < CH && (unsigned)gw < CW)
                v = xn[(size_t)(icb + ic) * CH * CW + gh * CW + gw];
            s_in[ic][r][c] = v;
        }

        // ---- stage weights: s_w[((ic*3+kh)*3+kw)*32 + oc] ----
        for (int idx = tid; idx < ICB * 9 * OC_TILE; idx += 256) {
            int oc = idx & 31;
            int t  = idx >> 5;        // 0..71
            int ic = t / 9;
            int k  = t - ic * 9;
            s_w[idx] = wgt[((size_t)(ocb + oc) * CC + (icb + ic)) * 9 + k];
        }
        __syncthreads();

        // ---- compute: per (ic, kh): 9 input LDS + 6 LDS.128 weights, 168 FFMA ----
#pragma unroll
        for (int ic = 0; ic < ICB; ic++) {
#pragma unroll
            for (int kh = 0; kh < 3; kh++) {
                float in[PW + 2];
                const float* ip = &s_in[ic][row + kh][wseg * PW];
#pragma unroll
                for (int p = 0; p < PW + 2; p++) in[p] = ip[p];

                const float* wp = &s_w[(ic * 9 + kh * 3) * OC_TILE + ocg * 8];
#pragma unroll
                for (int kw = 0; kw < 3; kw++) {
                    float4 wv0 = *(const float4*)(wp + kw * OC_TILE);
                    float4 wv1 = *(const float4*)(wp + kw * OC_TILE + 4);
                    float wv[8] = {wv0.x, wv0.y, wv0.z, wv0.w,
                                   wv1.x, wv1.y, wv1.z, wv1.w};
#pragma unroll
                    for (int o = 0; o < 8; o++)
#pragma unroll
                        for (int p = 0; p < PW; p++)
                            acc[o][p] = fmaf(in[p + kw], wv[o], acc[o][p]);
                }
            }
        }
    }

    // ---- epilogue: bias + store (7 contiguous floats per oc per thread) ----
    const int oh  = hb * H_TILE + row;
    const int ow0 = wb * W_TILE + wseg * PW;
#pragma unroll
    for (int o = 0; o < 8; o++) {
        int oc  = ocb + ocg * 8 + o;
        float b = bias[oc];
        float* op = out + (((size_t)n * CK + oc) * CH + oh) * CW + ow0;
#pragma unroll
        for (int p = 0; p < PW; p++) op[p] = acc[o][p] + b;
    }
}

extern "C" void kernel_launch(void* const* d_in, const int* in_sizes, int n_in,
                              void* d_out, int out_size) {
    const float* x    = (const float*)d_in[0];   // [32,64,112,112]
    const float* wgt  = (const float*)d_in[1];   // [128,64,3,3]
    const float* bias = (const float*)d_in[2];   // [128]
    float* out        = (float*)d_out;           // [32,128,112,112]

    dim3 grid(28 /* 7 hb * 4 wb */, CK / OC_TILE /* 4 */, CN /* 32 */);
    conv3x3_kernel<<<grid, 256>>>(x, wgt, bias, out);
}

// round 4
// speedup vs baseline: 1.1631x; 1.1631x over previous
#include <cuda_runtime.h>

// Conv2d 3x3, stride 1, pad 1, NCHW fp32 — packed f32x2 FFMA version.
// x: [32, 64, 112, 112], w: [128, 64, 3, 3], b: [128] -> out: [32, 128, 112, 112]

#define CN 32
#define CC 64
#define CH 112
#define CW 112
#define CK 128

#define OC_TILE 32   // output channels per block
#define H_TILE  16   // output rows per block
#define W_TILE  28   // output cols per block
#define ICB      8   // input-channel chunk staged in smem
#define PW       7   // pixels (width) per thread
#define IN_H    (H_TILE + 2)   // 18
#define IN_W    (W_TILE + 2)   // 30
#define IN_STRIDE 33           // padded row stride (bank-conflict break)

typedef unsigned long long u64;

// packed {v, v}
__device__ __forceinline__ u64 dup_f32x2(float v) {
    u64 d;
    asm("mov.b64 %0, {%1, %1};" : "=l"(d) : "f"(v));
    return d;
}

// d = a * b + c, lanewise fp32x2 (Blackwell packed-FFMA: 2 FMAs per issue)
__device__ __forceinline__ u64 ffma2(u64 a, u64 b, u64 c) {
    u64 d;
    asm("fma.rn.f32x2 %0, %1, %2, %3;" : "=l"(d) : "l"(a), "l"(b), "l"(c));
    return d;
}

__global__ __launch_bounds__(256, 2)
void conv3x3_kernel(const float* __restrict__ x,
                    const float* __restrict__ wgt,
                    const float* __restrict__ bias,
                    float* __restrict__ out) {
    __shared__ float s_in[ICB][IN_H][IN_STRIDE];          // 19,008 B
    __shared__ float s_w[ICB * 9 * OC_TILE];              //  9,216 B  layout [ic][kh][kw][oc]

    const int tid  = threadIdx.x;
    const int wseg = tid & 3;          // 0..3  -> w segment of 7
    const int row  = (tid >> 2) & 15;  // 0..15 -> output row in tile
    const int ocg  = tid >> 6;         // 0..3  -> group of 8 ocs

    const int sp = blockIdx.x;         // 0..27 = hb*4 + wb
    const int hb = sp >> 2;            // 0..6
    const int wb = sp & 3;             // 0..3
    const int ocb = blockIdx.y * OC_TILE;
    const int n   = blockIdx.z;

    const int h0 = hb * H_TILE - 1;    // input tile origin (with halo)
    const int w0 = wb * W_TILE - 1;

    // accumulators: 4 oc-pairs x 7 pixels, packed f32x2 {oc_even, oc_odd}
    u64 acc[4][PW];
#pragma unroll
    for (int q = 0; q < 4; q++)
#pragma unroll
        for (int p = 0; p < PW; p++) acc[q][p] = 0ull;

    const float* xn = x + (size_t)n * CC * CH * CW;

    for (int icb = 0; icb < CC; icb += ICB) {
        __syncthreads();   // protect smem from previous chunk's readers

        // ---- stage input tile: ICB x 18 x 30, zero-padded at image border ----
        for (int idx = tid; idx < ICB * IN_H * IN_W; idx += 256) {
            int ic  = idx / (IN_H * IN_W);
            int rem = idx - ic * (IN_H * IN_W);
            int r   = rem / IN_W;
            int c   = rem - r * IN_W;
            int gh  = h0 + r;
            int gw  = w0 + c;
            float v = 0.0f;
            if ((unsigned)gh < CH && (unsigned)gw < CW)
                v = xn[(size_t)(icb + ic) * CH * CW + gh * CW + gw];
            s_in[ic][r][c] = v;
        }

        // ---- stage weights: s_w[((ic*3+kh)*3+kw)*32 + oc] ----
        for (int idx = tid; idx < ICB * 9 * OC_TILE; idx += 256) {
            int oc = idx & 31;
            int t  = idx >> 5;        // 0..71
            int ic = t / 9;
            int k  = t - ic * 9;
            s_w[idx] = wgt[((size_t)(ocb + oc) * CC + (icb + ic)) * 9 + k];
        }
        __syncthreads();

        // ---- compute: per (ic,kh): 9 LDS + 9 dup + 6 LDS.128, 84 FFMA2 (=168 FMA) ----
#pragma unroll
        for (int ic = 0; ic < ICB; ic++) {
#pragma unroll
            for (int kh = 0; kh < 3; kh++) {
                const float* ip = &s_in[ic][row + kh][wseg * PW];
                u64 in2[PW + 2];
#pragma unroll
                for (int p = 0; p < PW + 2; p++) in2[p] = dup_f32x2(ip[p]);

                const float* wp = &s_w[(ic * 9 + kh * 3) * OC_TILE + ocg * 8];
#pragma unroll
                for (int kw = 0; kw < 3; kw++) {
                    // two LDS.128 -> four packed {w[2i], w[2i+1]} f32x2 operands
                    ulonglong2 wa = *(const ulonglong2*)(wp + kw * OC_TILE);
                    ulonglong2 wb2 = *(const ulonglong2*)(wp + kw * OC_TILE + 4);
                    u64 w2[4] = {wa.x, wa.y, wb2.x, wb2.y};
#pragma unroll
                    for (int q = 0; q < 4; q++)
#pragma unroll
                        for (int p = 0; p < PW; p++)
                            acc[q][p] = ffma2(in2[p + kw], w2[q], acc[q][p]);
                }
            }
        }
    }

    // ---- epilogue: unpack, bias + store (7 contiguous floats per oc) ----
    const int oh  = hb * H_TILE + row;
    const int ow0 = wb * W_TILE + wseg * PW;
#pragma unroll
    for (int q = 0; q < 4; q++) {
        int oc0 = ocb + ocg * 8 + 2 * q;
        float b0 = bias[oc0];
        float b1 = bias[oc0 + 1];
        float* op0 = out + (((size_t)n * CK + oc0) * CH + oh) * CW + ow0;
        float* op1 = op0 + (size_t)CH * CW;
#pragma unroll
        for (int p = 0; p < PW; p++) {
            float lo, hi;
            asm("mov.b64 {%0, %1}, %2;" : "=f"(lo), "=f"(hi) : "l"(acc[q][p]));
            op0[p] = lo + b0;
            op1[p] = hi + b1;
        }
    }
}

extern "C" void kernel_launch(void* const* d_in, const int* in_sizes, int n_in,
                              void* d_out, int out_size) {
    const float* x    = (const float*)d_in[0];   // [32,64,112,112]
    const float* wgt  = (const float*)d_in[1];   // [128,64,3,3]
    const float* bias = (const float*)d_in[2];   // [128]
    float* out        = (float*)d_out;           // [32,128,112,112]

    dim3 grid(28 /* 7 hb * 4 wb */, CK / OC_TILE /* 4 */, CN /* 32 */);
    conv3x3_kernel<<<grid, 256>>>(x, wgt, bias, out);
}

// round 7
// speedup vs baseline: 1.2720x; 1.0936x over previous
#include <cuda_runtime.h>

// Conv2d 3x3, stride 1, pad 1, NCHW fp32 — f32x2 FFMA + cp.async double-buffered.
// x: [32, 64, 112, 112], w: [128, 64, 3, 3], b: [128] -> out: [32, 128, 112, 112]

#define CN 32
#define CC 64
#define CH 112
#define CW 112
#define CK 128

#define OC_TILE 32
#define H_TILE  16
#define W_TILE  28
#define ICB      8
#define PW       7
#define IN_H    (H_TILE + 2)   // 18
#define IN_W    (W_TILE + 2)   // 30
#define IN_STRIDE 33           // bank-conflict break

#define IN_BUF   (ICB * IN_H * IN_STRIDE)   // 4752 floats
#define W_BUF    (ICB * 9 * OC_TILE)        // 2304 floats
#define SMEM_FLOATS (2 * IN_BUF + 2 * W_BUF)
#define SMEM_BYTES  (SMEM_FLOATS * 4)       // 56448

typedef unsigned long long u64;

__device__ __forceinline__ u64 dup_f32x2(float v) {
    u64 d;
    asm("mov.b64 %0, {%1, %1};" : "=l"(d) : "f"(v));
    return d;
}

__device__ __forceinline__ u64 ffma2(u64 a, u64 b, u64 c) {
    u64 d;
    asm("fma.rn.f32x2 %0, %1, %2, %3;" : "=l"(d) : "l"(a), "l"(b), "l"(c));
    return d;
}

__device__ __forceinline__ void cp_async4(unsigned dst, const void* src, bool ok) {
    int sz = ok ? 4 : 0;   // src-size 0 -> zero-fill destination
    asm volatile("cp.async.ca.shared.global [%0], [%1], 4, %2;"
                 :: "r"(dst), "l"(src), "r"(sz));
}

__device__ __forceinline__ void cp_commit() {
    asm volatile("cp.async.commit_group;");
}

__device__ __forceinline__ void cp_wait_all() {
    asm volatile("cp.async.wait_group 0;");
}

__global__ __launch_bounds__(256, 2)
void conv3x3_kernel(const float* __restrict__ x,
                    const float* __restrict__ wgt,
                    const float* __restrict__ bias,
                    float* __restrict__ out) {
    extern __shared__ float smem[];
    float* s_in_base = smem;                 // [2][IN_BUF]
    float* s_w_base  = smem + 2 * IN_BUF;    // [2][W_BUF]

    const int tid  = threadIdx.x;
    const int wseg = tid & 3;
    const int row  = (tid >> 2) & 15;
    const int ocg  = tid >> 6;

    const int sp = blockIdx.x;
    const int hb = sp >> 2;
    const int wb = sp & 3;
    const int ocb = blockIdx.y * OC_TILE;
    const int n   = blockIdx.z;

    const int h0 = hb * H_TILE - 1;
    const int w0 = wb * W_TILE - 1;

    const float* xn = x + (size_t)n * CC * CH * CW;

    // staging decomposition: 8 groups of 32 threads, one group per ic; lane = column
    const int st_ic = tid >> 5;            // 0..7
    const int st_c  = tid & 31;            // 0..31 (>=30 idle)
    const int st_gw = w0 + st_c;
    const bool st_wok = (st_c < IN_W) && ((unsigned)st_gw < CW);

    // ---- async stage of one chunk into buffer `buf` ----
    auto stage = [&](int icb, int buf) {
        float* si = s_in_base + buf * IN_BUF;
        float* sw = s_w_base  + buf * W_BUF;
        if (st_c < IN_W) {
            const float* src_base = xn + (size_t)(icb + st_ic) * CH * CW + st_gw;
            unsigned dst = (unsigned)__cvta_generic_to_shared(
                si + (st_ic * IN_H) * IN_STRIDE + st_c);
#pragma unroll
            for (int r = 0; r < IN_H; r++) {
                int gh = h0 + r;
                bool ok = st_wok && ((unsigned)gh < CH);
                const float* src = ok ? (src_base + gh * CW) : xn;
                cp_async4(dst, src, ok);
                dst += IN_STRIDE * 4;
            }
        }
#pragma unroll
        for (int j = 0; j < 9; j++) {
            int idx = j * 256 + tid;       // 0..2303
            int oc = idx & 31;
            int t  = idx >> 5;             // 0..71
            int ic = t / 9;
            int k  = t - ic * 9;
            cp_async4((unsigned)__cvta_generic_to_shared(sw + idx),
                      wgt + ((size_t)(ocb + oc) * CC + (icb + ic)) * 9 + k, true);
        }
        cp_commit();
    };

    u64 acc[4][PW];
#pragma unroll
    for (int q = 0; q < 4; q++)
#pragma unroll
        for (int p = 0; p < PW; p++) acc[q][p] = 0ull;

    stage(0, 0);

    int buf = 0;
    for (int cidx = 0; cidx < CC / ICB; cidx++) {
        cp_wait_all();
        __syncthreads();                    // chunk `cidx` visible to all threads

        if (cidx + 1 < CC / ICB)
            stage((cidx + 1) * ICB, buf ^ 1);   // overlap next stage with compute

        const float* si = s_in_base + buf * IN_BUF;
        const float* sw = s_w_base  + buf * W_BUF;

#pragma unroll
        for (int ic = 0; ic < ICB; ic++) {
#pragma unroll
            for (int kh = 0; kh < 3; kh++) {
                const float* ip = si + (ic * IN_H + row + kh) * IN_STRIDE + wseg * PW;
                u64 in2[PW + 2];
#pragma unroll
                for (int p = 0; p < PW + 2; p++) in2[p] = dup_f32x2(ip[p]);

                const float* wp = sw + (ic * 9 + kh * 3) * OC_TILE + ocg * 8;
#pragma unroll
                for (int kw = 0; kw < 3; kw++) {
                    ulonglong2 wa = *(const ulonglong2*)(wp + kw * OC_TILE);
                    ulonglong2 wb2 = *(const ulonglong2*)(wp + kw * OC_TILE + 4);
                    u64 w2[4] = {wa.x, wa.y, wb2.x, wb2.y};
#pragma unroll
                    for (int q = 0; q < 4; q++)
#pragma unroll
                        for (int p = 0; p < PW; p++)
                            acc[q][p] = ffma2(in2[p + kw], w2[q], acc[q][p]);
                }
            }
        }
        __syncthreads();                    // done reading `buf` before its re-stage
        buf ^= 1;
    }

    // ---- epilogue: unpack, bias + store ----
    const int oh  = hb * H_TILE + row;
    const int ow0 = wb * W_TILE + wseg * PW;
#pragma unroll
    for (int q = 0; q < 4; q++) {
        int oc0 = ocb + ocg * 8 + 2 * q;
        float b0 = bias[oc0];
        float b1 = bias[oc0 + 1];
        float* op0 = out + (((size_t)n * CK + oc0) * CH + oh) * CW + ow0;
        float* op1 = op0 + (size_t)CH * CW;
#pragma unroll
        for (int p = 0; p < PW; p++) {
            float lo, hi;
            asm("mov.b64 {%0, %1}, %2;" : "=f"(lo), "=f"(hi) : "l"(acc[q][p]));
            op0[p] = lo + b0;
            op1[p] = hi + b1;
        }
    }
}

extern "C" void kernel_launch(void* const* d_in, const int* in_sizes, int n_in,
                              void* d_out, int out_size) {
    const float* x    = (const float*)d_in[0];
    const float* wgt  = (const float*)d_in[1];
    const float* bias = (const float*)d_in[2];
    float* out        = (float*)d_out;

    // Unconditional + idempotent; no stream work, safe outside and irrelevant
    // during graph capture (harness captures only the launch below).
    cudaFuncSetAttribute(conv3x3_kernel,
                         cudaFuncAttributeMaxDynamicSharedMemorySize, SMEM_BYTES);

    dim3 grid(28, CK / OC_TILE, CN);
    conv3x3_kernel<<<grid, 256, SMEM_BYTES>>>(x, wgt, bias, out);
}